// round 1
// baseline (speedup 1.0000x reference)
#include <cuda_runtime.h>
#include <cuda_bf16.h>
#include <cstdint>

// Conv 3x3, stride 1, pad 1, NHWC.  N=32, H=W=56, Cin=128, Cout=256.
// Implicit GEMM: M = 32*56*56 = 100352, N = 256, K = 9*128 = 1152.
// C[m][co] = sum_k A[m][k] * B[k][co];  A = im2col(input), B = filter (K-major, co contiguous).
// Then + bias, ReLU.

#define CONV_H   56
#define CONV_W   56
#define CONV_NB  32
#define CONV_CIN 128
#define CONV_COUT 256

#define BM 64
#define BN 64
#define BK 32
#define NKTILES 36   // 1152 / 32

__global__ __launch_bounds__(256, 2)
void conv3x3_igemm_kernel(const float* __restrict__ in,
                          const float* __restrict__ wt,
                          const float* __restrict__ bias,
                          float* __restrict__ out)
{
    // As transposed [kk][m], padded to 65 so the scalar transpose-stores
    // (threads sharing arow, acol stride 8 -> addr stride 8*65=520, %32 = 8 banks apart)
    // are conflict-free. Bs is [kk][co], float4-friendly.
    __shared__ __align__(16) float As[2][BK][BM + 1];
    __shared__ __align__(16) float Bs[2][BK][BN];

    const int tid = threadIdx.x;
    const int tx = tid & 15;        // 0..15 -> output-channel quad
    const int ty = tid >> 4;        // 0..15 -> output-row quad

    // ---- A (im2col) load mapping: thread -> (row, 8 contiguous ci) ----
    const int arow = tid >> 2;            // 0..63
    const int acol = (tid & 3) << 3;      // 0,8,16,24
    const int m    = blockIdx.y * BM + arow;   // M = 100352 divisible by 64
    const int n    = m / (CONV_H * CONV_W);
    const int hw   = m % (CONV_H * CONV_W);
    const int h    = hw / CONV_W;
    const int w    = hw % CONV_W;

    // ---- B (filter) load mapping ----
    const int brow  = tid >> 3;           // 0..31  (k within tile)
    const int bcol  = (tid & 7) << 3;     // 0,8,...,56
    const int cbase = blockIdx.x * BN;

    float4 ra0, ra1, rb0, rb1;

    // prologue: tile 0
    {
        const int k0  = 0;
        const int ci0 = 0;
        // f = 0 -> fh = 0, fw = 0 -> ih = h-1, iw = w-1
        const int ih = h - 1, iw = w - 1;
        const bool valid = ((unsigned)ih < CONV_H) && ((unsigned)iw < CONV_W);
        if (valid) {
            const float* p = in + (((size_t)(n * CONV_H + ih) * CONV_W + iw) * CONV_CIN + ci0 + acol);
            ra0 = *reinterpret_cast<const float4*>(p);
            ra1 = *reinterpret_cast<const float4*>(p + 4);
        } else {
            ra0 = make_float4(0.f, 0.f, 0.f, 0.f);
            ra1 = ra0;
        }
        const float* q = wt + ((size_t)(k0 + brow) * CONV_COUT + cbase + bcol);
        rb0 = *reinterpret_cast<const float4*>(q);
        rb1 = *reinterpret_cast<const float4*>(q + 4);
    }
    // store tile 0 into buffer 0
    {
        As[0][acol + 0][arow] = ra0.x;
        As[0][acol + 1][arow] = ra0.y;
        As[0][acol + 2][arow] = ra0.z;
        As[0][acol + 3][arow] = ra0.w;
        As[0][acol + 4][arow] = ra1.x;
        As[0][acol + 5][arow] = ra1.y;
        As[0][acol + 6][arow] = ra1.z;
        As[0][acol + 7][arow] = ra1.w;
        *reinterpret_cast<float4*>(&Bs[0][brow][bcol])     = rb0;
        *reinterpret_cast<float4*>(&Bs[0][brow][bcol + 4]) = rb1;
    }
    __syncthreads();

    float acc[4][4];
#pragma unroll
    for (int i = 0; i < 4; i++)
#pragma unroll
        for (int j = 0; j < 4; j++) acc[i][j] = 0.f;

    int buf = 0;
#pragma unroll 1
    for (int kt = 0; kt < NKTILES; kt++) {
        // prefetch tile kt+1 into registers (overlaps with compute below)
        if (kt + 1 < NKTILES) {
            const int k0  = (kt + 1) * BK;
            const int f   = k0 >> 7;        // k0 / 128
            const int ci0 = k0 & 127;
            const int fh  = f / 3;
            const int fw  = f - fh * 3;
            const int ih  = h + fh - 1;
            const int iw  = w + fw - 1;
            const bool valid = ((unsigned)ih < CONV_H) && ((unsigned)iw < CONV_W);
            if (valid) {
                const float* p = in + (((size_t)(n * CONV_H + ih) * CONV_W + iw) * CONV_CIN + ci0 + acol);
                ra0 = *reinterpret_cast<const float4*>(p);
                ra1 = *reinterpret_cast<const float4*>(p + 4);
            } else {
                ra0 = make_float4(0.f, 0.f, 0.f, 0.f);
                ra1 = ra0;
            }
            const float* q = wt + ((size_t)(k0 + brow) * CONV_COUT + cbase + bcol);
            rb0 = *reinterpret_cast<const float4*>(q);
            rb1 = *reinterpret_cast<const float4*>(q + 4);
        }

        // compute on current buffer
#pragma unroll
        for (int kk = 0; kk < BK; kk++) {
            float av0 = As[buf][kk][ty * 4 + 0];
            float av1 = As[buf][kk][ty * 4 + 1];
            float av2 = As[buf][kk][ty * 4 + 2];
            float av3 = As[buf][kk][ty * 4 + 3];
            float4 bv = *reinterpret_cast<const float4*>(&Bs[buf][kk][tx * 4]);
            acc[0][0] = fmaf(av0, bv.x, acc[0][0]);
            acc[0][1] = fmaf(av0, bv.y, acc[0][1]);
            acc[0][2] = fmaf(av0, bv.z, acc[0][2]);
            acc[0][3] = fmaf(av0, bv.w, acc[0][3]);
            acc[1][0] = fmaf(av1, bv.x, acc[1][0]);
            acc[1][1] = fmaf(av1, bv.y, acc[1][1]);
            acc[1][2] = fmaf(av1, bv.z, acc[1][2]);
            acc[1][3] = fmaf(av1, bv.w, acc[1][3]);
            acc[2][0] = fmaf(av2, bv.x, acc[2][0]);
            acc[2][1] = fmaf(av2, bv.y, acc[2][1]);
            acc[2][2] = fmaf(av2, bv.z, acc[2][2]);
            acc[2][3] = fmaf(av2, bv.w, acc[2][3]);
            acc[3][0] = fmaf(av3, bv.x, acc[3][0]);
            acc[3][1] = fmaf(av3, bv.y, acc[3][1]);
            acc[3][2] = fmaf(av3, bv.z, acc[3][2]);
            acc[3][3] = fmaf(av3, bv.w, acc[3][3]);
        }

        // publish prefetched tile into the other buffer
        if (kt + 1 < NKTILES) {
            const int nb = buf ^ 1;
            As[nb][acol + 0][arow] = ra0.x;
            As[nb][acol + 1][arow] = ra0.y;
            As[nb][acol + 2][arow] = ra0.z;
            As[nb][acol + 3][arow] = ra0.w;
            As[nb][acol + 4][arow] = ra1.x;
            As[nb][acol + 5][arow] = ra1.y;
            As[nb][acol + 6][arow] = ra1.z;
            As[nb][acol + 7][arow] = ra1.w;
            *reinterpret_cast<float4*>(&Bs[nb][brow][bcol])     = rb0;
            *reinterpret_cast<float4*>(&Bs[nb][brow][bcol + 4]) = rb1;
            __syncthreads();
            buf = nb;
        }
    }

    // epilogue: bias + ReLU, float4 stores
    const int ocol = cbase + tx * 4;
    const float4 bv = *reinterpret_cast<const float4*>(&bias[ocol]);
    const int orow0 = blockIdx.y * BM + ty * 4;
#pragma unroll
    for (int i = 0; i < 4; i++) {
        float4 r;
        r.x = fmaxf(acc[i][0] + bv.x, 0.f);
        r.y = fmaxf(acc[i][1] + bv.y, 0.f);
        r.z = fmaxf(acc[i][2] + bv.z, 0.f);
        r.w = fmaxf(acc[i][3] + bv.w, 0.f);
        *reinterpret_cast<float4*>(&out[(size_t)(orow0 + i) * CONV_COUT + ocol]) = r;
    }
}

extern "C" void kernel_launch(void* const* d_in, const int* in_sizes, int n_in,
                              void* d_out, int out_size)
{
    const float* prev_a  = (const float*)d_in[0];  // [32,56,56,128]
    const float* filter_w = (const float*)d_in[1]; // [3,3,128,256] -> [K=1152][256]
    const float* filter_b = (const float*)d_in[2]; // [256]
    float* out = (float*)d_out;                    // [32,56,56,256]

    dim3 grid(CONV_COUT / BN, (CONV_NB * CONV_H * CONV_W) / BM);  // (4, 1568)
    conv3x3_igemm_kernel<<<grid, 256>>>(prev_a, filter_w, filter_b, out);
}

// round 3
// speedup vs baseline: 5.0911x; 5.0911x over previous
#include <cuda_runtime.h>
#include <cstdint>

// Conv 3x3 s1 p1 NHWC: N=32,H=W=56,Cin=128,Cout=256  (fp32 in/out)
// Implicit GEMM via tcgen05 kind::tf32:
//   M = 32*56*56 = 100352, N = 256, K = 9*128 = 1152
// Prep: pad input -> g_pad[32][58][58][128] (tf32-rounded), transpose filter ->
// g_bt[256][1152] (tf32-rounded). Main: per CTA M_tile=256 (2x128 accums in
// TMEM, 512 cols), N_tile=256 (2x N=128 MMAs), BK=32, triple-buffered SMEM via
// cp.async, mbarrier-tracked MMA completion, LDTM epilogue + bias + ReLU.
//
// The tcgen05 body is guarded by __CUDA_ARCH_FEAT_SM103_ALL so the generic
// compute_103 PTX pass (which rejects tcgen05) compiles a correct FFMA
// fallback into the same kernel symbol instead.

#define H_    56
#define W_    56
#define NB_   32
#define CIN   128
#define COUT  256
#define KTOT  1152
#define BK    32
#define NKT   36              // 1152/32
#define MTILE 256
#define GRIDM 392             // 100352/256

// idesc kind::tf32: dtype=F32(1)<<4 | atype=TF32(2)<<7 | btype=TF32(2)<<10
//                   | (N/8=16)<<17 | (M/16=8)<<24
#define IDESC_TF32 0x8200910u

__device__ float g_pad[(size_t)NB_ * 58 * 58 * CIN];   // 55.1 MB
__device__ float g_bt[(size_t)COUT * KTOT];            // 1.18 MB

// ---------------- small PTX helpers (sm_80+-safe ones unguarded) ----------------
__device__ __forceinline__ uint32_t smem_u32(const void* p) {
    uint32_t a;
    asm("{ .reg .u64 t; cvta.to.shared.u64 t, %1; cvt.u32.u64 %0, t; }" : "=r"(a) : "l"(p));
    return a;
}
__device__ __forceinline__ uint32_t elect_one() {
    uint32_t p;
    asm volatile("{ .reg .pred p; elect.sync _|p, 0xFFFFFFFF; selp.b32 %0, 1, 0, p; }" : "=r"(p));
    return p;
}
__device__ __forceinline__ float to_tf32(float x) {
    uint32_t u;
    asm("cvt.rna.tf32.f32 %0, %1;" : "=r"(u) : "f"(x));
    return __uint_as_float(u);
}
__device__ __forceinline__ void cp16(uint32_t dst, const float* src) {
    asm volatile("cp.async.cg.shared.global [%0], [%1], 16;" :: "r"(dst), "l"(src));
}
__device__ __forceinline__ void cp_commit() {
    asm volatile("cp.async.commit_group;" ::: "memory");
}
__device__ __forceinline__ void mbar_init(uint32_t a, uint32_t cnt) {
    asm volatile("mbarrier.init.shared.b64 [%0], %1;" :: "r"(a), "r"(cnt) : "memory");
}
__device__ __forceinline__ void mbar_wait(uint32_t a, uint32_t parity) {
    asm volatile(
        "{\n\t.reg .pred P1;\n\t"
        "WL%=:\n\t"
        "mbarrier.try_wait.parity.acquire.cta.shared::cta.b64 P1, [%0], %1, 0x989680;\n\t"
        "@P1 bra.uni WD%=;\n\t"
        "bra.uni WL%=;\n\t"
        "WD%=:\n\t}"
        :: "r"(a), "r"(parity) : "memory");
}
__device__ __forceinline__ uint32_t swz(uint32_t off) { return off ^ ((off >> 3) & 0x70); }

// 64b SMEM descriptor: SW128, version=1, SBO=64, LBO=1 (K-major, 128B rows)
__device__ __forceinline__ uint64_t make_desc(uint32_t addr) {
    const uint64_t base = (uint64_t(2) << 61) | (uint64_t(1) << 46)
                        | (uint64_t(64) << 32) | (uint64_t(1) << 16);
    return base | ((uint64_t)(addr >> 4) & 0x3FFF);
}

// ---- tcgen05 helpers: only referenced inside the feature-guarded branch, so
// they are discarded (never lowered to PTX) on the generic compute_103 pass.
__device__ __forceinline__ void mma_tf32_ss(uint32_t d, uint64_t ad, uint64_t bd,
                                            uint32_t idesc, uint32_t en) {
    asm volatile(
        "{\n\t.reg .pred p;\n\t"
        "setp.ne.u32 p, %4, 0;\n\t"
        "tcgen05.mma.cta_group::1.kind::tf32 [%0], %1, %2, %3, {%5, %5, %5, %5}, p;\n\t}"
        :: "r"(d), "l"(ad), "l"(bd), "r"(idesc), "r"(en), "r"(0u) : "memory");
}
__device__ __forceinline__ void tc_commit(uint32_t mbar) {
    asm volatile(
        "tcgen05.commit.cta_group::1.mbarrier::arrive::one.shared::cluster.b64 [%0];"
        :: "r"(mbar) : "memory");
}

// ---------------- prep kernels ----------------
__global__ void prep_pad(const float* __restrict__ in) {
    int idx = blockIdx.x * 256 + threadIdx.x;      // float4 index
    int pix = idx >> 5;
    int c0  = (idx & 31) << 2;                     // float offset in channel dim
    int n   = pix / (58 * 58);
    int r   = pix % (58 * 58);
    int hp  = r / 58, wp = r % 58;
    float4 v = make_float4(0.f, 0.f, 0.f, 0.f);
    if (hp >= 1 && hp <= 56 && wp >= 1 && wp <= 56) {
        v = *reinterpret_cast<const float4*>(
            in + (((size_t)n * H_ + (hp - 1)) * W_ + (wp - 1)) * CIN + c0);
        v.x = to_tf32(v.x); v.y = to_tf32(v.y);
        v.z = to_tf32(v.z); v.w = to_tf32(v.w);
    }
    reinterpret_cast<float4*>(g_pad)[idx] = v;
}

__global__ void prep_bt(const float* __restrict__ wt) {
    int idx = blockIdx.x * 256 + threadIdx.x;      // over 256*1152
    int nn = idx / KTOT, k = idx % KTOT;
    g_bt[idx] = to_tf32(wt[(size_t)k * COUT + nn]);
}

// ---------------- main kernel ----------------
// SMEM (relative to 1KB-aligned base):
//   0:    u32 tmem_ptr
//   8:    u64 mbar[4]   (buf0,buf1,buf2,final)
//   64:   float bias[256]
//   2048: 3 buffers x 64KB: { A0 16KB | A1 16KB | B 32KB }
#define SM_TMEMPTR 0
#define SM_MBAR    8
#define SM_BIAS    64
#define SM_TILES   2048
#define TILE_STRIDE 65536
#define A1_OFF 16384
#define B_OFF  32768
#define SMEM_ALLOC (1024 + SM_TILES + 3 * TILE_STRIDE)   // incl. align slack

__global__ __launch_bounds__(256, 1)
void conv_main(const float* __restrict__ bias, float* __restrict__ out)
{
    extern __shared__ char smem_raw[];

#if !defined(__CUDA_ARCH__) || defined(__CUDA_ARCH_FEAT_SM103_ALL) || defined(__CUDA_ARCH_FEAT_SM103A_ALL)
    // ================== tcgen05 tf32 path (sm_103a cubin) ==================
    uint32_t sraw = smem_u32(smem_raw);
    uint32_t pad  = (1024u - (sraw & 1023u)) & 1023u;
    char*    sm   = smem_raw + pad;
    uint32_t s1k  = sraw + pad;

    const int tid = threadIdx.x;
    const int wid = tid >> 5;
    const int lane = tid & 31;

    if (tid == 0) {
        #pragma unroll
        for (int i = 0; i < 4; i++) mbar_init(s1k + SM_MBAR + 8 * i, 1);
    }
    if (wid == 0) {
        asm volatile("tcgen05.alloc.cta_group::1.sync.aligned.shared::cta.b32 [%0], %1;"
                     :: "r"(s1k + SM_TMEMPTR), "r"(512u) : "memory");
        asm volatile("tcgen05.relinquish_alloc_permit.cta_group::1.sync.aligned;");
    }
    float* bias_s = reinterpret_cast<float*>(sm + SM_BIAS);
    bias_s[tid] = bias[tid];
    __syncthreads();

    uint32_t tmem;
    asm volatile("ld.shared.b32 %0, [%1];" : "=r"(tmem) : "r"(s1k + SM_TMEMPTR));

    // ---- per-thread load mappings ----
    // A: 2 accum tiles x 128 rows x 32 floats; thread -> (row = tid>>1, 4 float4)
    const int arow = tid >> 1;
    const int af4  = (tid & 1) * 4;                 // first float4 col (of 8)
    const float* pA[2];
    #pragma unroll
    for (int a = 0; a < 2; a++) {
        int m  = blockIdx.x * MTILE + a * 128 + arow;
        int n  = m / (H_ * W_);
        int hw = m - n * (H_ * W_);
        int h  = hw / W_;
        int w  = hw - h * W_;
        pA[a] = g_pad + (((size_t)n * 58 + h) * 58 + w) * CIN;
    }
    // B: thread -> row tid, 8 float4 of the 32-float K-slice
    const float* pB = g_bt + (size_t)tid * KTOT;

    uint32_t tbase[3];
    #pragma unroll
    for (int s = 0; s < 3; s++) tbase[s] = s1k + SM_TILES + s * TILE_STRIDE;

    // ---- tile loader ----
    auto load_tile = [&](int kt, int s) {
        int f   = kt >> 2;
        int fh  = f / 3;
        int fw  = f - fh * 3;
        int ci0 = (kt & 3) << 5;
        size_t goff = ((size_t)fh * 58 + fw) * CIN + ci0 + af4 * 4;
        #pragma unroll
        for (int a = 0; a < 2; a++) {
            const float* src = pA[a] + goff;
            uint32_t db = tbase[s] + a * A1_OFF;
            #pragma unroll
            for (int i = 0; i < 4; i++)
                cp16(db + swz(arow * 128 + (af4 + i) * 16), src + i * 4);
        }
        {
            const float* src = pB + kt * BK;
            uint32_t db = tbase[s] + B_OFF;
            #pragma unroll
            for (int i = 0; i < 8; i++)
                cp16(db + swz(tid * 128 + i * 16), src + i * 4);
        }
        cp_commit();
    };

    // preload tiles 0,1
    load_tile(0, 0);
    load_tile(1, 1);

    int phase0 = 0, phase1 = 0, phase2 = 0;

    #pragma unroll 1
    for (int kt = 0; kt < NKT; kt++) {
        const int s = kt % 3;

        // stage tile kt+2 (its buffer was last used by tile kt-1)
        if (kt + 2 < NKT) {
            int b = (kt + 2) % 3;
            if (kt >= 1) {
                if (b == 0)      { mbar_wait(s1k + SM_MBAR + 0,  phase0); phase0 ^= 1; }
                else if (b == 1) { mbar_wait(s1k + SM_MBAR + 8,  phase1); phase1 ^= 1; }
                else             { mbar_wait(s1k + SM_MBAR + 16, phase2); phase2 ^= 1; }
            }
            load_tile(kt + 2, b);
        }

        // tile kt resident?
        if (kt <= NKT - 3)      asm volatile("cp.async.wait_group 2;" ::: "memory");
        else if (kt == NKT - 2) asm volatile("cp.async.wait_group 1;" ::: "memory");
        else                    asm volatile("cp.async.wait_group 0;" ::: "memory");
        asm volatile("fence.proxy.async.shared::cta;" ::: "memory");
        __syncthreads();

        if (wid == 0 && elect_one()) {
            uint64_t ad0 = make_desc(tbase[s]);
            uint64_t ad1 = make_desc(tbase[s] + A1_OFF);
            uint64_t bd0 = make_desc(tbase[s] + B_OFF);
            uint64_t bd1 = make_desc(tbase[s] + B_OFF + 16384);
            #pragma unroll
            for (int ks = 0; ks < 4; ks++) {
                uint32_t en = (kt > 0 || ks > 0) ? 1u : 0u;
                mma_tf32_ss(tmem +   0, ad0 + ks * 2, bd0 + ks * 2, IDESC_TF32, en);
                mma_tf32_ss(tmem + 128, ad0 + ks * 2, bd1 + ks * 2, IDESC_TF32, en);
                mma_tf32_ss(tmem + 256, ad1 + ks * 2, bd0 + ks * 2, IDESC_TF32, en);
                mma_tf32_ss(tmem + 384, ad1 + ks * 2, bd1 + ks * 2, IDESC_TF32, en);
            }
            tc_commit(s1k + SM_MBAR + 8 * s);
        }
    }

    // final completion barrier
    if (wid == 0 && elect_one()) tc_commit(s1k + SM_MBAR + 24);
    mbar_wait(s1k + SM_MBAR + 24, 0);
    asm volatile("tcgen05.fence::after_thread_sync;" ::: "memory");

    // ---- epilogue: 8 warps; warps 0-3 -> accum 0, 4-7 -> accum 1 ----
    const int a   = wid >> 2;
    const int wig = wid & 3;
    const uint32_t woff = (uint32_t)wig << 21;
    const int m = blockIdx.x * MTILE + a * 128 + wig * 32 + lane;
    float* orow = out + (size_t)m * COUT;

    #pragma unroll 1
    for (int ch = 0; ch < 8; ch++) {
        uint32_t r[32];
        asm volatile(
            "tcgen05.ld.sync.aligned.32x32b.x32.b32 "
            "{%0, %1, %2, %3, %4, %5, %6, %7, "
            " %8, %9, %10, %11, %12, %13, %14, %15, "
            " %16, %17, %18, %19, %20, %21, %22, %23, "
            " %24, %25, %26, %27, %28, %29, %30, %31}, [%32];"
            : "=r"(r[0]),  "=r"(r[1]),  "=r"(r[2]),  "=r"(r[3]),
              "=r"(r[4]),  "=r"(r[5]),  "=r"(r[6]),  "=r"(r[7]),
              "=r"(r[8]),  "=r"(r[9]),  "=r"(r[10]), "=r"(r[11]),
              "=r"(r[12]), "=r"(r[13]), "=r"(r[14]), "=r"(r[15]),
              "=r"(r[16]), "=r"(r[17]), "=r"(r[18]), "=r"(r[19]),
              "=r"(r[20]), "=r"(r[21]), "=r"(r[22]), "=r"(r[23]),
              "=r"(r[24]), "=r"(r[25]), "=r"(r[26]), "=r"(r[27]),
              "=r"(r[28]), "=r"(r[29]), "=r"(r[30]), "=r"(r[31])
            : "r"(tmem + a * 256 + ch * 32 + woff));
        asm volatile("tcgen05.wait::ld.sync.aligned;" ::: "memory");

        const int c0 = ch * 32;
        #pragma unroll
        for (int j = 0; j < 8; j++) {
            float4 v;
            v.x = fmaxf(__uint_as_float(r[4*j+0]) + bias_s[c0 + 4*j + 0], 0.f);
            v.y = fmaxf(__uint_as_float(r[4*j+1]) + bias_s[c0 + 4*j + 1], 0.f);
            v.z = fmaxf(__uint_as_float(r[4*j+2]) + bias_s[c0 + 4*j + 2], 0.f);
            v.w = fmaxf(__uint_as_float(r[4*j+3]) + bias_s[c0 + 4*j + 3], 0.f);
            *reinterpret_cast<float4*>(orow + c0 + 4*j) = v;
        }
    }

    __syncthreads();
    if (wid == 0) {
        asm volatile("tcgen05.dealloc.cta_group::1.sync.aligned.b32 %0, %1;"
                     :: "r"(tmem), "r"(512u));
    }

#else
    // ============ generic fallback (compute_103 PTX pass): FFMA tiles ============
    // Same symbol, same launch config; only used if the runtime ever JITs the
    // generic PTX instead of loading the sm_103a cubin.
    char* sm = smem_raw;
    float* As = reinterpret_cast<float*>(sm);            // [32][65]
    float* Bs = As + 32 * 65;                            // [64][33]

    const int tid = threadIdx.x;
    const int ty = tid >> 4, tx = tid & 15;
    const int arow = tid >> 2;           // 0..63
    const int acol = (tid & 3) * 8;      // A: 8 floats
    const int bn   = tid >> 2;           // 0..63
    const int bk   = (tid & 3) * 8;      // B: 8 floats

    for (int nc = 0; nc < 4; nc++) {
        const int cbase = nc * 64;
        for (int mc = 0; mc < 4; mc++) {
            const int m  = blockIdx.x * MTILE + mc * 64 + arow;
            const int n  = m / (H_ * W_);
            const int hw = m - n * (H_ * W_);
            const int h  = hw / W_;
            const int w  = hw - h * W_;
            const float* pa = g_pad + (((size_t)n * 58 + h) * 58 + w) * CIN;

            float acc[4][4];
            #pragma unroll
            for (int i = 0; i < 4; i++)
                #pragma unroll
                for (int j = 0; j < 4; j++) acc[i][j] = 0.f;

            for (int kt = 0; kt < NKT; kt++) {
                __syncthreads();
                const int f = kt >> 2, fh = f / 3, fw = f - fh * 3;
                const int ci0 = (kt & 3) << 5;
                const float* src = pa + ((size_t)fh * 58 + fw) * CIN + ci0 + acol;
                #pragma unroll
                for (int i = 0; i < 8; i++) As[(acol + i) * 65 + arow] = src[i];
                const float* bsrc = g_bt + (size_t)(cbase + bn) * KTOT + kt * BK + bk;
                #pragma unroll
                for (int i = 0; i < 8; i++) Bs[bn * 33 + bk + i] = bsrc[i];
                __syncthreads();
                #pragma unroll
                for (int kk = 0; kk < BK; kk++) {
                    float a0 = As[kk * 65 + ty * 4 + 0];
                    float a1 = As[kk * 65 + ty * 4 + 1];
                    float a2 = As[kk * 65 + ty * 4 + 2];
                    float a3 = As[kk * 65 + ty * 4 + 3];
                    float b0 = Bs[(tx * 4 + 0) * 33 + kk];
                    float b1 = Bs[(tx * 4 + 1) * 33 + kk];
                    float b2 = Bs[(tx * 4 + 2) * 33 + kk];
                    float b3 = Bs[(tx * 4 + 3) * 33 + kk];
                    acc[0][0] = fmaf(a0, b0, acc[0][0]); acc[0][1] = fmaf(a0, b1, acc[0][1]);
                    acc[0][2] = fmaf(a0, b2, acc[0][2]); acc[0][3] = fmaf(a0, b3, acc[0][3]);
                    acc[1][0] = fmaf(a1, b0, acc[1][0]); acc[1][1] = fmaf(a1, b1, acc[1][1]);
                    acc[1][2] = fmaf(a1, b2, acc[1][2]); acc[1][3] = fmaf(a1, b3, acc[1][3]);
                    acc[2][0] = fmaf(a2, b0, acc[2][0]); acc[2][1] = fmaf(a2, b1, acc[2][1]);
                    acc[2][2] = fmaf(a2, b2, acc[2][2]); acc[2][3] = fmaf(a2, b3, acc[2][3]);
                    acc[3][0] = fmaf(a3, b0, acc[3][0]); acc[3][1] = fmaf(a3, b1, acc[3][1]);
                    acc[3][2] = fmaf(a3, b2, acc[3][2]); acc[3][3] = fmaf(a3, b3, acc[3][3]);
                }
            }

            const int ocol = cbase + tx * 4;
            const int orow0 = blockIdx.x * MTILE + mc * 64 + ty * 4;
            #pragma unroll
            for (int i = 0; i < 4; i++) {
                #pragma unroll
                for (int j = 0; j < 4; j++) {
                    out[(size_t)(orow0 + i) * COUT + ocol + j] =
                        fmaxf(acc[i][j] + bias[ocol + j], 0.f);
                }
            }
            __syncthreads();
        }
    }
#endif
}

// ---------------- launch ----------------
extern "C" void kernel_launch(void* const* d_in, const int* in_sizes, int n_in,
                              void* d_out, int out_size)
{
    const float* prev_a   = (const float*)d_in[0];  // [32,56,56,128]
    const float* filter_w = (const float*)d_in[1];  // [3,3,128,256]
    const float* filter_b = (const float*)d_in[2];  // [256]
    float* out = (float*)d_out;                     // [100352,256]

    cudaFuncSetAttribute(conv_main, cudaFuncAttributeMaxDynamicSharedMemorySize, SMEM_ALLOC);

    prep_pad<<<13456, 256>>>(prev_a);               // 3,444,736 float4
    prep_bt<<<1152, 256>>>(filter_w);               // 294,912 floats
    conv_main<<<GRIDM, 256, SMEM_ALLOC>>>(filter_b, out);
}